// round 12
// baseline (speedup 1.0000x reference)
#include <cuda_runtime.h>
#include <cstddef>

#define SEQ   512
#define BATCH 4096
#define INDIM 9
#define HID   64
#define OUTD  10
#define NTH   256                       // 8 warps: 0-3 pI, 4-5 L2, 6-7 L1
#define BLKS  16                        // steps per phase
#define NBLK  (SEQ/BLKS)                // 32
#define NPH   (NBLK + 2)                // 34 phases (3-stage pipeline)
#define RING  32                        // ring rows (2 blocks)
#define CSCALE 2.885390081777927f       // 2/ln2
#define WSCALE (-2.0f * CSCALE)

// shared memory float offsets
#define O_HIST  0                          // SEQ*HID : xw' -> r2 history
#define O_XS    (O_HIST + SEQ*HID)         // SEQ*INDIM
#define O_RING  (O_XS + SEQ*INDIM)         // RING*HID  r1 ring
#define O_PIR   (O_RING + RING*HID)        // RING*HID  pI ring (reduced + base2)
#define O_R2    (O_PIR + RING*HID)         // 2*HID     r2 double buffer
#define O_RS1   (O_R2 + 2*HID)             // HID
#define O_WFC   (O_RS1 + HID)              // OUTD*HID (scaled -2)
#define O_BFC   (O_WFC + OUTD*HID)         // 16
#define SM_FLOATS (O_BFC + 16)
#define SM_BYTES  (SM_FLOATS * 4)

typedef unsigned long long ull;

__device__ __forceinline__ ull ffma2(ull a, ull b, ull c) {
    ull d; asm("fma.rn.f32x2 %0, %1, %2, %3;" : "=l"(d) : "l"(a), "l"(b), "l"(c));
    return d;
}
__device__ __forceinline__ ull fadd2(ull a, ull b) {
    ull d; asm("add.rn.f32x2 %0, %1, %2;" : "=l"(d) : "l"(a), "l"(b));
    return d;
}
__device__ __forceinline__ float f2sum(ull a) {
    float2 f = *reinterpret_cast<float2*>(&a);
    return f.x + f.y;
}
__device__ __forceinline__ ull pack2(float x, float y) {
    ull r; asm("mov.b64 %0, {%1,%2};" : "=l"(r) : "f"(x), "f"(y));
    return r;
}
// r = 1/(e^{2s}+1) with input pre-scaled by 2/ln2; tanh(s) = 1 - 2r
__device__ __forceinline__ float sig_r(float in) {
    float e, r;
    asm("ex2.approx.f32 %0, %1;" : "=f"(e) : "f"(in));
    asm("rcp.approx.f32 %0, %1;" : "=f"(r) : "f"(e + 1.0f));
    return r;
}
#define BAR_L1() asm volatile("bar.sync 1, 64;" ::: "memory")
#define BAR_L2() asm volatile("bar.sync 2, 64;" ::: "memory")

// SCALAR 64-dot, seeded: 16 LDS.128, 64 FFMA (rt2/lat4), 8 accums depth 8
__device__ __forceinline__ float sdot64_seed(const float* __restrict__ w,
                                             const float* __restrict__ src,
                                             float seed) {
    const float4* hp = reinterpret_cast<const float4*>(src);
    float a0=0.f, a1=0.f, a2=0.f, a3=0.f, a4=0.f, a5=0.f, a6=0.f, a7=seed;
    #pragma unroll
    for (int q = 0; q < 16; q += 2) {
        float4 u = hp[q], v = hp[q+1];
        a0 = fmaf(u.x, w[4*q+0], a0);
        a1 = fmaf(u.y, w[4*q+1], a1);
        a2 = fmaf(u.z, w[4*q+2], a2);
        a3 = fmaf(u.w, w[4*q+3], a3);
        a4 = fmaf(v.x, w[4*q+4], a4);
        a5 = fmaf(v.y, w[4*q+5], a5);
        a6 = fmaf(v.z, w[4*q+6], a6);
        a7 = fmaf(v.w, w[4*q+7], a7);
    }
    return ((a0 + a1) + (a2 + a3)) + ((a4 + a5) + (a6 + a7));
}

// packed 32-long half dot for pI (off critical path): 8 LDS.128, 16 FFMA2
__device__ __forceinline__ float dot32h(const ull* __restrict__ w,
                                        const float* __restrict__ src) {
    const ulonglong2* hp = reinterpret_cast<const ulonglong2*>(src);
    ull a0 = 0ull, a1 = 0ull, a2 = 0ull, a3 = 0ull;
    #pragma unroll
    for (int q = 0; q < 4; ++q) {
        ulonglong2 u = hp[2*q], v = hp[2*q+1];
        a0 = ffma2(u.x, w[4*q+0], a0);
        a1 = ffma2(u.y, w[4*q+1], a1);
        a2 = ffma2(v.x, w[4*q+2], a2);
        a3 = ffma2(v.y, w[4*q+3], a3);
    }
    return f2sum(fadd2(fadd2(a0, a1), fadd2(a2, a3)));
}

// scalar scaled weight row load: 64 floats
__device__ __forceinline__ void load_wrow_scalar(const float* __restrict__ W, int u,
                                                 float* __restrict__ w) {
    const float4* p = reinterpret_cast<const float4*>(W + (size_t)u * HID);
    #pragma unroll
    for (int q = 0; q < 16; ++q) {
        float4 v = p[q];
        w[4*q+0] = v.x * WSCALE;
        w[4*q+1] = v.y * WSCALE;
        w[4*q+2] = v.z * WSCALE;
        w[4*q+3] = v.w * WSCALE;
    }
}

__global__ __launch_bounds__(NTH, 1)
void rnn_motion_kernel(const float* __restrict__ x,
                       const float* __restrict__ Wih0, const float* __restrict__ Whh0,
                       const float* __restrict__ bih0, const float* __restrict__ bhh0,
                       const float* __restrict__ Wih1, const float* __restrict__ Whh1,
                       const float* __restrict__ bih1, const float* __restrict__ bhh1,
                       const float* __restrict__ Wfc,  const float* __restrict__ bfc_g,
                       float* __restrict__ out)
{
    extern __shared__ float sm[];
    float* hist = sm + O_HIST;
    float* xs   = sm + O_XS;
    float* ring = sm + O_RING;
    float* pir  = sm + O_PIR;
    float* r2b  = sm + O_R2;
    float* rs1  = sm + O_RS1;
    float* wfc  = sm + O_WFC;
    float* bfc  = sm + O_BFC;

    const int tid  = threadIdx.x;
    const int wid  = tid >> 5;
    const int lane = tid & 31;

    // ---- prologue A ----
    for (int e = tid; e < SEQ*INDIM; e += NTH) {
        int t = e / INDIM, k = e % INDIM;
        xs[e] = x[((size_t)t * BATCH + (BATCH - 1)) * INDIM + k];
    }
    for (int e = tid; e < OUTD*HID; e += NTH) wfc[e] = -2.0f * Wfc[e];
    if (tid < HID) {
        ring[(RING-1)*HID + tid] = 0.5f;    // r1(-1): h=0 <-> r=0.5
        r2b[HID + tid]           = 0.5f;    // r2(-1), parity 1
        const float4* p = reinterpret_cast<const float4*>(Whh0 + (size_t)tid * HID);
        float s = 0.f;
        #pragma unroll
        for (int q = 0; q < 16; ++q) { float4 v = p[q]; s += (v.x+v.y)+(v.z+v.w); }
        rs1[tid] = s;                       // rowsum(Whh0_i)
    }
    if (tid < OUTD) {                       // bfc'[o] = bfc + rowsum(Wfc_o)
        const float4* p = reinterpret_cast<const float4*>(Wfc + (size_t)tid * HID);
        float s = bfc_g[tid];
        #pragma unroll
        for (int q = 0; q < 16; ++q) { float4 v = p[q]; s += (v.x+v.y)+(v.z+v.w); }
        bfc[tid] = s;
    }
    __syncthreads();

    // ---- prologue B: xw'[t][i] = C*(x_t.Wih0_i + b_ih0 + b_hh0 + rowsum(Whh0_i)) ----
    {
        const int ii = tid & (HID-1);
        float wi[INDIM];
        #pragma unroll
        for (int k = 0; k < INDIM; ++k) wi[k] = CSCALE * Wih0[ii*INDIM + k];
        const float bb = CSCALE * (bih0[ii] + bhh0[ii] + rs1[ii]);
        for (int t = tid >> 6; t < SEQ; t += NTH/HID) {
            float s = bb;
            #pragma unroll
            for (int k = 0; k < INDIM; ++k) s += xs[t*INDIM + k] * wi[k];
            hist[t*HID + ii] = s;
        }
    }
    __syncthreads();

    // ==================== 3-stage pipelined scan ====================
    if (wid >= 6) {
        // ===== L1 pair (warps 6,7): unit i, 64 scalar FFMA/step =====
        const int i = ((wid - 6) << 5) | lane;
        float w1[64];
        load_wrow_scalar(Whh0, i, w1);
        for (int m = 0; m < NPH; ++m) {
            if (m < NBLK) {
                const int t0 = m * BLKS;
                const float* src = ring + ((t0 - 1) & (RING-1)) * HID;
                float*       dst = ring + (t0 & (RING-1)) * HID;
                float xwreg[BLKS];                       // block prefetch, off-chain
                {
                    const float* xwp = hist + t0*HID + i;
                    #pragma unroll
                    for (int j = 0; j < BLKS; ++j) xwreg[j] = xwp[j*HID];
                }
                #pragma unroll 2
                for (int j = 0; j < BLKS; ++j) {
                    float s = sdot64_seed(w1, src, xwreg[j]);
                    float r = sig_r(s);
                    dst[i] = r;
                    BAR_L1();
                    src = dst; dst += HID;
                }
            }
            __syncthreads();
        }
    } else if (wid >= 4) {
        // ===== L2 pair (warps 4,5): unit i, 64 scalar FFMA/step, pI+base2 seeded =====
        const int i = ((wid - 4) << 5) | lane;
        float wh[64];
        load_wrow_scalar(Whh1, i, wh);
        for (int m = 0; m < NPH; ++m) {
            if (m >= 2) {
                const int s0 = (m - 2) * BLKS;          // even
                const float* pip = pir + (s0 & (RING-1)) * HID + i;
                float*       hw  = hist + s0*HID + i;
                #pragma unroll 1
                for (int jj = 0; jj < BLKS/2; ++jj) {
                    {   // s even: read r2 parity 1, write parity 0
                        float pi = *pip;                // LDS first: covers the seed
                        float s = sdot64_seed(wh, r2b + HID, pi);
                        float r = sig_r(s);
                        r2b[i] = r; *hw = r;
                        BAR_L2();
                        pip += HID; hw += HID;
                    }
                    {   // s odd: read parity 0, write parity 1
                        float pi = *pip;
                        float s = sdot64_seed(wh, r2b, pi);
                        float r = sig_r(s);
                        r2b[HID + i] = r; *hw = r;
                        BAR_L2();
                        pip += HID; hw += HID;
                    }
                }
            }
            __syncthreads();
        }
    } else {
        // ===== pI quad (wid 0-3): stores Wih1.r1 + base2; 1 block behind =====
        const int u = (wid << 4) | (lane & 15);         // unit
        const int h = lane >> 4;                        // input half
        const int off = h << 5;
        ull wi2[16];
        float rsHalf;                                   // rowsum of Wih1+Whh1 half-rows
        {
            const float4* p = reinterpret_cast<const float4*>(Wih1 + (size_t)u * HID + off);
            float s = 0.f;
            #pragma unroll
            for (int q = 0; q < 8; ++q) {
                float4 v = p[q];
                s += (v.x+v.y)+(v.z+v.w);
                wi2[2*q]   = pack2(v.x*WSCALE, v.y*WSCALE);
                wi2[2*q+1] = pack2(v.z*WSCALE, v.w*WSCALE);
            }
            const float4* p2 = reinterpret_cast<const float4*>(Whh1 + (size_t)u * HID + off);
            #pragma unroll
            for (int q = 0; q < 8; ++q) {
                float4 v = p2[q];
                s += (v.x+v.y)+(v.z+v.w);
            }
            rsHalf = s;
        }
        float rsFull = rsHalf + __shfl_xor_sync(0xffffffffu, rsHalf, 16);
        const float base2 = CSCALE * (bih1[u] + bhh1[u] + rsFull);
        for (int m = 0; m < NPH; ++m) {
            if (m >= 1 && m < NBLK + 1) {
                const int s0 = (m - 1) * BLKS;
                const float* rrow = ring + (s0 & (RING-1)) * HID + off;
                float*       pip  = pir  + (s0 & (RING-1)) * HID + u;
                #pragma unroll 2
                for (int j = 0; j < BLKS; ++j) {
                    float p = dot32h(wi2, rrow);
                    p += __shfl_xor_sync(0xffffffffu, p, 16);
                    *pip = p + base2;               // both halves write same value
                    rrow += HID; pip += HID;
                }
            }
            __syncthreads();
        }
    }
    __syncthreads();

    // ---- epilogue: out[t][o] = bfc'[o] + sum_k r2[t][k] * (-2*Wfc[o][k]) ----
    #pragma unroll
    for (int m = 0; m < SEQ/NTH; ++m) {
        const int t = tid + NTH * m;
        const float4* h4 = reinterpret_cast<const float4*>(hist + t*HID);
        #pragma unroll
        for (int o = 0; o < OUTD; ++o) {
            const float4* w4 = reinterpret_cast<const float4*>(wfc + o*HID);
            float s0 = bfc[o], s1 = 0.f, s2 = 0.f, s3 = 0.f;
            #pragma unroll
            for (int q = 0; q < HID/4; ++q) {
                float4 hv = h4[q], wv = w4[q];
                s0 = fmaf(hv.x, wv.x, s0);
                s1 = fmaf(hv.y, wv.y, s1);
                s2 = fmaf(hv.z, wv.z, s2);
                s3 = fmaf(hv.w, wv.w, s3);
            }
            out[t*OUTD + o] = (s0 + s1) + (s2 + s3);
        }
    }
}

extern "C" void kernel_launch(void* const* d_in, const int* in_sizes, int n_in,
                              void* d_out, int out_size) {
    (void)in_sizes; (void)n_in; (void)out_size;
    const float* x    = (const float*)d_in[0];
    const float* Wih0 = (const float*)d_in[1];
    const float* Whh0 = (const float*)d_in[2];
    const float* bih0 = (const float*)d_in[3];
    const float* bhh0 = (const float*)d_in[4];
    const float* Wih1 = (const float*)d_in[5];
    const float* Whh1 = (const float*)d_in[6];
    const float* bih1 = (const float*)d_in[7];
    const float* bhh1 = (const float*)d_in[8];
    const float* Wfc  = (const float*)d_in[9];
    const float* bfc  = (const float*)d_in[10];
    float* out = (float*)d_out;

    cudaFuncSetAttribute(rnn_motion_kernel,
                         cudaFuncAttributeMaxDynamicSharedMemorySize, SM_BYTES);
    rnn_motion_kernel<<<1, NTH, SM_BYTES>>>(
        x, Wih0, Whh0, bih0, bhh0, Wih1, Whh1, bih1, bhh1, Wfc, bfc, out);
}